// round 11
// baseline (speedup 1.0000x reference)
#include <cuda_runtime.h>
#include <cuda_fp16.h>

// LNCC loss, two-pass separable:
//   pass1: block = 2 d-planes x 160 cols (320 thr), H-strip of 40 (NH=4).
//          cp.async 8-row ring (dist 6, wait_group 4), 2 rows/barrier.
//          One 9-tap W sum per thread (9 LDS.64), fp16-bit H sliding
//          history -> 10 B/voxel fp16 scratch.
//   pass2: R8 structure: thread owns 2 adjacent w cols, depth-4 lead
//          prefetch (LDG.128+LDG.32) + L1-hit trail reload (jd-9), ND=8
//          for occupancy, reg-capped. NCC + fused reduction/finalize.

#define BB 2
#define DD 160
#define HH 160
#define WW 160
#define VOLSZ (DD*HH*WW)
#define VOL2  (BB*VOLSZ)

#define NH 4
#define HS (HH/NH)          // 40 output rows per block
#define ROWS (HS + 8)       // 48 row steps

#define ND 8
#define DS (DD/ND)          // 20
#define STEPS (DS + 8)      // 28

#define P2_BLOCKS ((HH/2) * ND * BB)   // 1280

__device__ __align__(16) uint2          g_scrA[VOL2];   // {half2(Sx,Sy), half2(Sxx,Syy)}
__device__ __align__(16) unsigned short g_scrC[VOL2];   // half(Sxy)
__device__ double g_acc;
__device__ unsigned int g_ctr;

// ---- packed f32x2 helpers (sm_100+) ----
typedef unsigned long long ull;
__device__ __forceinline__ ull pk2(float a, float b) {
    ull r; asm("mov.b64 %0, {%1, %2};" : "=l"(r) : "f"(a), "f"(b)); return r;
}
__device__ __forceinline__ void upk2(ull v, float& a, float& b) {
    asm("mov.b64 {%0, %1}, %2;" : "=f"(a), "=f"(b) : "l"(v));
}
__device__ __forceinline__ ull add2(ull a, ull b) {
    ull d; asm("add.rn.f32x2 %0, %1, %2;" : "=l"(d) : "l"(a), "l"(b)); return d;
}
__device__ __forceinline__ ull sub2(ull a, ull b) {
    ull d; asm("sub.rn.f32x2 %0, %1, %2;" : "=l"(d) : "l"(a), "l"(b)); return d;
}
__device__ __forceinline__ ull mul2(ull a, ull b) {
    ull d; asm("mul.rn.f32x2 %0, %1, %2;" : "=l"(d) : "l"(a), "l"(b)); return d;
}
__device__ __forceinline__ ull fma2(ull a, ull b, ull c) {
    ull d; asm("fma.rn.f32x2 %0, %1, %2, %3;" : "=l"(d) : "l"(a), "l"(b), "l"(c)); return d;
}

__device__ __forceinline__ int iclamp(int v, int hi) { return min(max(v, 0), hi); }

__device__ __forceinline__ float2 h2f(unsigned bits) {
    __half2 h = *reinterpret_cast<__half2*>(&bits);
    return __half22float2(h);
}
__device__ __forceinline__ unsigned f2hbits(float a, float b) {
    __half2 h = __floats2half2_rn(a, b);
    return *reinterpret_cast<unsigned*>(&h);
}

__device__ __forceinline__ void cpa4(void* dst_smem, const void* src) {
    unsigned s = (unsigned)__cvta_generic_to_shared(dst_smem);
    asm volatile("cp.async.ca.shared.global [%0], [%1], 4;" :: "r"(s), "l"(src));
}
#define CPA_COMMIT() asm volatile("cp.async.commit_group;" ::: "memory")
#define CPA_WAIT4()  asm volatile("cp.async.wait_group 4;" ::: "memory")

// slide one packed field through fp16-bit history (exact add/sub round trip)
__device__ __forceinline__ void slide_p(ull s, unsigned& hist, ull& run) {
    float f0, f1; upk2(s, f0, f1);
    const unsigned nb = f2hbits(f0, f1);
    const float2 nf = h2f(nb);
    const float2 of = h2f(hist);
    run = add2(run, sub2(pk2(nf.x, nf.y), pk2(of.x, of.y)));
    hist = nb;
}
__device__ __forceinline__ unsigned pack_run(ull run) {
    float f0, f1; upk2(run, f0, f1);
    return f2hbits(f0, f1);
}

// ================= pass 1: 320 threads, 1 column/thread =================
__global__ __launch_bounds__(320, 3)
void lncc_pass1(const float* __restrict__ x, const float* __restrict__ y) {
    __shared__ __align__(16) float2 buf[2][8][WW + 8];

    const int tid = threadIdx.x;
    const int ty  = tid / 160;           // plane select
    const int tx  = tid % 160;           // column

    const int strip = blockIdx.x;
    const int d     = blockIdx.y * 2 + ty;
    const int b     = blockIdx.z;
    const int hs0   = strip * HS;

    if (blockIdx.x == 0 && blockIdx.y == 0 && blockIdx.z == 0 && tid == 0) {
        g_acc = 0.0;
        g_ctr = 0u;
    }

    const float* xp = x + ((size_t)b * DD + d) * (HH * WW);
    const float* yp = y + ((size_t)b * DD + d) * (HH * WW);

    const int gw  = iclamp(tx - 4, WW - 1);
    const int gw2 = min(156 + tx, WW - 1);      // used when tx < 8

    auto issue = [&](int r) {
        const int gh = iclamp(hs0 - 4 + r, HH - 1);
        const float* xr = xp + gh * WW;
        const float* yr = yp + gh * WW;
        float2* dst = buf[ty][r & 7];
        cpa4(&dst[tx].x, xr + gw);
        cpa4(&dst[tx].y, yr + gw);
        if (tx < 8) {
            cpa4(&dst[WW + tx].x, xr + gw2);
            cpa4(&dst[WW + tx].y, yr + gw2);
        }
        CPA_COMMIT();
    };

    issue(0); issue(1); issue(2); issue(3); issue(4); issue(5);

    // fp16-bit history: A=(Sx,Sy), B=(Sxx,Syy); fp32 Sxy
    unsigned hA[9], hB[9];
    float hXY[9];
    #pragma unroll
    for (int k = 0; k < 9; ++k) { hA[k]=0u; hB[k]=0u; hXY[k]=0.f; }
    ull rA = 0ull, rB = 0ull;
    float rxy = 0.f;

    const size_t obase = ((size_t)b * DD + d) * (HH * WW) + tx;

    #pragma unroll
    for (int it = 0; it < ROWS / 2; ++it) {
        CPA_WAIT4();
        __syncthreads();

        if (2 * it + 6 < ROWS) issue(2 * it + 6); else CPA_COMMIT();
        if (2 * it + 7 < ROWS) issue(2 * it + 7); else CPA_COMMIT();

        #pragma unroll
        for (int sub = 0; sub < 2; ++sub) {
            const int r = 2 * it + sub;
            const float2* row = buf[ty][r & 7];

            ull s01 = 0ull, s23 = 0ull;
            float sxy = 0.f;
            #pragma unroll
            for (int t = 0; t < 9; ++t) {
                const float2 p = row[tx + t];
                const ull pp = pk2(p.x, p.y);
                s01 = add2(s01, pp);
                s23 = fma2(pp, pp, s23);
                sxy = fmaf(p.x, p.y, sxy);
            }

            const int k = r % 9;   // static per unrolled iteration
            slide_p(s01, hA[k], rA);
            slide_p(s23, hB[k], rB);
            rxy += sxy - hXY[k];   hXY[k] = sxy;

            if (r >= 8) {
                uint2 rec;
                rec.x = pack_run(rA);
                rec.y = pack_run(rB);
                const size_t o = obase + (size_t)(hs0 + r - 8) * WW;
                g_scrA[o] = rec;
                g_scrC[o] = (unsigned short)(f2hbits(rxy, 0.f) & 0xffffu);
            }
        }
    }
}

// ================= pass 2 helpers =================
__device__ __forceinline__ float ncc_term(ull runA, ull runB, float rxy) {
    const float invn = 1.0f / 729.0f;
    float sx, sy, sxx, syy;
    upk2(runA, sx, sy);
    upk2(runB, sxx, syy);
    const float xm = sx * invn;
    const float ym = sy * invn;
    const float cross = fmaf(-xm, ym, rxy * invn);
    const float vx    = fmaf(-xm, xm, sxx * invn);
    const float vy    = fmaf(-ym, ym, syy * invn);
    return __fdividef(cross * cross, fmaf(vx, vy, 1e-5f));
}

// ================= pass 2: D sliding + NCC + reduction + finalize ============
__global__ __launch_bounds__(160, 6)
void lncc_pass2(float* __restrict__ out) {
    const int tid = threadIdx.x;         // 0..159
    const int ty  = tid / 80;            // h row
    const int txp = tid % 80;            // w pair
    const int h   = blockIdx.x * 2 + ty;
    const int dc  = blockIdx.y;
    const int b   = blockIdx.z;
    const int d0  = dc * DS;
    const int w0  = txp * 2;

    const size_t base = (size_t)b * VOLSZ + (size_t)h * WW + w0;

    auto sidx = [&](int jd) -> size_t {
        const int gd = iclamp(d0 - 4 + jd, DD - 1);
        return base + (size_t)gd * (HH * WW);
    };

    // depth-4 lead prefetch: one uint4 (2 records' A) + one uint (2 Sxy)
    uint4 pipeA[4];
    unsigned pipeC[4];
    #pragma unroll
    for (int i = 0; i < 4; ++i) {
        const size_t idx = sidx(i);
        pipeA[i] = __ldg(reinterpret_cast<const uint4*>(&g_scrA[idx]));
        pipeC[i] = __ldg(reinterpret_cast<const unsigned*>(&g_scrC[idx]));
    }

    ull runA0 = 0ull, runB0 = 0ull, runA1 = 0ull, runB1 = 0ull;
    float runxy0 = 0.f, runxy1 = 0.f;
    float acc = 0.f;

    auto consume = [&](int jd, bool trail, bool emit) {
        const uint4    A = pipeA[jd & 3];
        const unsigned C = pipeC[jd & 3];
        if (jd + 4 < STEPS) {
            const size_t idx = sidx(jd + 4);
            pipeA[jd & 3] = __ldg(reinterpret_cast<const uint4*>(&g_scrA[idx]));
            pipeC[jd & 3] = __ldg(reinterpret_cast<const unsigned*>(&g_scrC[idx]));
        }
        uint4 T = make_uint4(0u, 0u, 0u, 0u);
        unsigned Tc = 0u;
        if (trail) {                      // record from step jd-9: L1/L2 hit
            const size_t idx = sidx(jd - 9);
            T  = __ldg(reinterpret_cast<const uint4*>(&g_scrA[idx]));
            Tc = __ldg(reinterpret_cast<const unsigned*>(&g_scrC[idx]));
        }
        {
            const float2 a = h2f(A.x), oa = h2f(T.x);
            const float2 q = h2f(A.y), oq = h2f(T.y);
            runA0 = add2(runA0, sub2(pk2(a.x, a.y), pk2(oa.x, oa.y)));
            runB0 = add2(runB0, sub2(pk2(q.x, q.y), pk2(oq.x, oq.y)));
        }
        {
            const float2 a = h2f(A.z), oa = h2f(T.z);
            const float2 q = h2f(A.w), oq = h2f(T.w);
            runA1 = add2(runA1, sub2(pk2(a.x, a.y), pk2(oa.x, oa.y)));
            runB1 = add2(runB1, sub2(pk2(q.x, q.y), pk2(oq.x, oq.y)));
        }
        {
            const float2 c = h2f(C), oc = h2f(Tc);
            runxy0 += c.x - oc.x;
            runxy1 += c.y - oc.y;
        }
        if (emit) {
            acc += ncc_term(runA0, runB0, runxy0);
            acc += ncc_term(runA1, runB1, runxy1);
        }
    };

    #pragma unroll
    for (int jd = 0; jd < 8; ++jd) consume(jd, false, false);
    consume(8, false, true);
    #pragma unroll 8
    for (int jd = 9; jd < STEPS; ++jd) consume(jd, true, true);

    // block reduce (5 warps) -> double atomic -> fused finalize
    __shared__ float red[5];
    #pragma unroll
    for (int o = 16; o > 0; o >>= 1)
        acc += __shfl_down_sync(0xffffffffu, acc, o);
    const int warp = tid >> 5;
    const int lane = tid & 31;
    if (lane == 0) red[warp] = acc;
    __syncthreads();
    if (warp == 0 && lane == 0) {
        float v = red[0] + red[1] + red[2] + red[3] + red[4];
        atomicAdd(&g_acc, (double)v);
        __threadfence();
        const unsigned ticket = atomicAdd(&g_ctr, 1u);
        if (ticket == (unsigned)(P2_BLOCKS - 1)) {
            double total = atomicAdd(&g_acc, 0.0);   // ordered read
            out[0] = (float)(-total * (1.0 / (double)VOL2));
        }
    }
}

extern "C" void kernel_launch(void* const* d_in, const int* in_sizes, int n_in,
                              void* d_out, int out_size) {
    (void)in_sizes; (void)n_in; (void)out_size;
    const float* x = (const float*)d_in[0];
    const float* y = (const float*)d_in[1];
    float* out = (float*)d_out;

    dim3 g1(NH, DD / 2, BB);      // 4 x 80 x 2 = 640 blocks, 320 thr
    lncc_pass1<<<g1, 320>>>(x, y);

    dim3 g2(HH / 2, ND, BB);      // 80 x 8 x 2 = 1280 blocks, 160 thr
    lncc_pass2<<<g2, 160>>>(out);
}

// round 12
// speedup vs baseline: 1.2440x; 1.2440x over previous
#include <cuda_runtime.h>
#include <cuda_fp16.h>

// LNCC loss, two-pass separable — best measured halves combined:
//   pass1 (R8): block = 2 d-planes x 80 w-pairs, H-strip of 40 (NH=4).
//          cp.async 8-row ring (dist 6, wait_group 4), 2 rows/barrier.
//          Two adjacent 9-tap W sums per thread (shared taps, 5 LDS.128),
//          fp16-bit H sliding history -> 10 B/voxel fp16 scratch.
//   pass2 (R11): thread owns 2 adjacent w cols, D-chunk 20 (ND=8), depth-4
//          lead prefetch (LDG.128+LDG.32) + L1-hit trail reload (jd-9),
//          reg-capped to 6 blocks/SM. NCC + fused reduction/finalize.

#define BB 2
#define DD 160
#define HH 160
#define WW 160
#define VOLSZ (DD*HH*WW)
#define VOL2  (BB*VOLSZ)

#define NH 4
#define HS (HH/NH)          // 40 output rows per block
#define ROWS (HS + 8)       // 48 row steps

#define ND 8
#define DS (DD/ND)          // 20
#define STEPS (DS + 8)      // 28

#define P2_BLOCKS ((HH/2) * ND * BB)   // 1280

__device__ __align__(16) uint2          g_scrA[VOL2];   // {half2(Sx,Sy), half2(Sxx,Syy)}
__device__ __align__(16) unsigned short g_scrC[VOL2];   // half(Sxy)
__device__ double g_acc;
__device__ unsigned int g_ctr;

// ---- packed f32x2 helpers (sm_100+) ----
typedef unsigned long long ull;
__device__ __forceinline__ ull pk2(float a, float b) {
    ull r; asm("mov.b64 %0, {%1, %2};" : "=l"(r) : "f"(a), "f"(b)); return r;
}
__device__ __forceinline__ void upk2(ull v, float& a, float& b) {
    asm("mov.b64 {%0, %1}, %2;" : "=f"(a), "=f"(b) : "l"(v));
}
__device__ __forceinline__ ull add2(ull a, ull b) {
    ull d; asm("add.rn.f32x2 %0, %1, %2;" : "=l"(d) : "l"(a), "l"(b)); return d;
}
__device__ __forceinline__ ull sub2(ull a, ull b) {
    ull d; asm("sub.rn.f32x2 %0, %1, %2;" : "=l"(d) : "l"(a), "l"(b)); return d;
}
__device__ __forceinline__ ull mul2(ull a, ull b) {
    ull d; asm("mul.rn.f32x2 %0, %1, %2;" : "=l"(d) : "l"(a), "l"(b)); return d;
}
__device__ __forceinline__ ull fma2(ull a, ull b, ull c) {
    ull d; asm("fma.rn.f32x2 %0, %1, %2, %3;" : "=l"(d) : "l"(a), "l"(b), "l"(c)); return d;
}

__device__ __forceinline__ int iclamp(int v, int hi) { return min(max(v, 0), hi); }

__device__ __forceinline__ float2 h2f(unsigned bits) {
    __half2 h = *reinterpret_cast<__half2*>(&bits);
    return __half22float2(h);
}
__device__ __forceinline__ unsigned f2hbits(float a, float b) {
    __half2 h = __floats2half2_rn(a, b);
    return *reinterpret_cast<unsigned*>(&h);
}

__device__ __forceinline__ void cpa4(void* dst_smem, const void* src) {
    unsigned s = (unsigned)__cvta_generic_to_shared(dst_smem);
    asm volatile("cp.async.ca.shared.global [%0], [%1], 4;" :: "r"(s), "l"(src));
}
#define CPA_COMMIT() asm volatile("cp.async.commit_group;" ::: "memory")
#define CPA_WAIT4()  asm volatile("cp.async.wait_group 4;" ::: "memory")

// slide one packed field through fp16-bit history (exact add/sub round trip)
__device__ __forceinline__ void slide_p(ull s, unsigned& hist, ull& run) {
    float f0, f1; upk2(s, f0, f1);
    const unsigned nb = f2hbits(f0, f1);
    const float2 nf = h2f(nb);
    const float2 of = h2f(hist);
    run = add2(run, sub2(pk2(nf.x, nf.y), pk2(of.x, of.y)));
    hist = nb;
}
__device__ __forceinline__ unsigned pack_run(ull run) {
    float f0, f1; upk2(run, f0, f1);
    return f2hbits(f0, f1);
}

// ================= pass 1 (R8) =================
__global__ __launch_bounds__(160)
void lncc_pass1(const float* __restrict__ x, const float* __restrict__ y) {
    __shared__ __align__(16) float2 buf[2][8][WW + 8];

    const int tid = threadIdx.x;
    const int ty  = tid / 80;            // plane select
    const int txp = tid % 80;            // w pair
    const int w0  = txp * 2;

    const int strip = blockIdx.x;
    const int d     = blockIdx.y * 2 + ty;
    const int b     = blockIdx.z;
    const int hs0   = strip * HS;

    if (blockIdx.x == 0 && blockIdx.y == 0 && blockIdx.z == 0 && tid == 0) {
        g_acc = 0.0;
        g_ctr = 0u;
    }

    const float* xp = x + ((size_t)b * DD + d) * (HH * WW);
    const float* yp = y + ((size_t)b * DD + d) * (HH * WW);

    auto issue = [&](int r) {
        const int gh = iclamp(hs0 - 4 + r, HH - 1);
        const float* xr = xp + gh * WW;
        const float* yr = yp + gh * WW;
        float2* dst = buf[ty][r & 7];
        #pragma unroll
        for (int e0 = 0; e0 < 3; ++e0) {
            const int e = txp + e0 * 80;
            if (e < WW + 8) {
                const int gw = iclamp(e - 4, WW - 1);
                cpa4(&dst[e].x, xr + gw);
                cpa4(&dst[e].y, yr + gw);
            }
        }
        CPA_COMMIT();
    };

    issue(0); issue(1); issue(2); issue(3); issue(4); issue(5);

    // fp16-bit history: per column A=(Sx,Sy), B=(Sxx,Syy); shared XY pair
    unsigned hA0[9], hB0[9], hA1[9], hB1[9], hXY[9];
    #pragma unroll
    for (int k = 0; k < 9; ++k) { hA0[k]=0u; hB0[k]=0u; hA1[k]=0u; hB1[k]=0u; hXY[k]=0u; }
    ull rA0 = 0ull, rB0 = 0ull, rA1 = 0ull, rB1 = 0ull;
    float rxy0 = 0.f, rxy1 = 0.f;

    const size_t obase = ((size_t)b * DD + d) * (HH * WW) + w0;

    #pragma unroll
    for (int it = 0; it < ROWS / 2; ++it) {
        CPA_WAIT4();
        __syncthreads();

        if (2 * it + 6 < ROWS) issue(2 * it + 6); else CPA_COMMIT();
        if (2 * it + 7 < ROWS) issue(2 * it + 7); else CPA_COMMIT();

        #pragma unroll
        for (int sub = 0; sub < 2; ++sub) {
            const int r = 2 * it + sub;
            const float4* row4 = reinterpret_cast<const float4*>(buf[ty][r & 7]);

            // taps e = w0 .. w0+9  (float4 = two (x,y) pairs)
            const float4 q0 = row4[txp];
            const float4 q1 = row4[txp + 1];
            const float4 q2 = row4[txp + 2];
            const float4 q3 = row4[txp + 3];
            const float4 q4 = row4[txp + 4];

            const ull pp0 = pk2(q0.x, q0.y), pp1 = pk2(q0.z, q0.w);
            const ull pp2 = pk2(q1.x, q1.y), pp3 = pk2(q1.z, q1.w);
            const ull pp4 = pk2(q2.x, q2.y), pp5 = pk2(q2.z, q2.w);
            const ull pp6 = pk2(q3.x, q3.y), pp7 = pk2(q3.z, q3.w);
            const ull pp8 = pk2(q4.x, q4.y), pp9 = pk2(q4.z, q4.w);

            // column 0: taps 0..8
            ull s01 = add2(pp0, pp1);
            s01 = add2(s01, pp2); s01 = add2(s01, pp3); s01 = add2(s01, pp4);
            s01 = add2(s01, pp5); s01 = add2(s01, pp6); s01 = add2(s01, pp7);
            s01 = add2(s01, pp8);
            ull s23 = mul2(pp0, pp0);
            s23 = fma2(pp1, pp1, s23); s23 = fma2(pp2, pp2, s23);
            s23 = fma2(pp3, pp3, s23); s23 = fma2(pp4, pp4, s23);
            s23 = fma2(pp5, pp5, s23); s23 = fma2(pp6, pp6, s23);
            s23 = fma2(pp7, pp7, s23); s23 = fma2(pp8, pp8, s23);
            float sxy0 = q0.x * q0.y;
            sxy0 = fmaf(q0.z, q0.w, sxy0); sxy0 = fmaf(q1.x, q1.y, sxy0);
            sxy0 = fmaf(q1.z, q1.w, sxy0); sxy0 = fmaf(q2.x, q2.y, sxy0);
            sxy0 = fmaf(q2.z, q2.w, sxy0); sxy0 = fmaf(q3.x, q3.y, sxy0);
            sxy0 = fmaf(q3.z, q3.w, sxy0); sxy0 = fmaf(q4.x, q4.y, sxy0);

            // column 1: taps 1..9 = col0 - tap0 + tap9
            const ull s01b = add2(sub2(s01, pp0), pp9);
            const ull s23b = fma2(pp9, pp9, sub2(s23, mul2(pp0, pp0)));
            const float sxy1 = fmaf(q4.z, q4.w, fmaf(-q0.x, q0.y, sxy0));

            const int k = r % 9;   // static per unrolled iteration
            slide_p(s01,  hA0[k], rA0);
            slide_p(s23,  hB0[k], rB0);
            slide_p(s01b, hA1[k], rA1);
            slide_p(s23b, hB1[k], rB1);
            {
                const unsigned nb = f2hbits(sxy0, sxy1);
                const float2 nf = h2f(nb);
                const float2 of = h2f(hXY[k]);
                rxy0 += nf.x - of.x;
                rxy1 += nf.y - of.y;
                hXY[k] = nb;
            }

            if (r >= 8) {
                uint4 rec;
                rec.x = pack_run(rA0);
                rec.y = pack_run(rB0);
                rec.z = pack_run(rA1);
                rec.w = pack_run(rB1);
                const size_t o = obase + (size_t)(hs0 + r - 8) * WW;
                *reinterpret_cast<uint4*>(&g_scrA[o]) = rec;
                *reinterpret_cast<unsigned*>(&g_scrC[o]) = f2hbits(rxy0, rxy1);
            }
        }
    }
}

// ================= pass 2 helpers =================
__device__ __forceinline__ float ncc_term(ull runA, ull runB, float rxy) {
    const float invn = 1.0f / 729.0f;
    float sx, sy, sxx, syy;
    upk2(runA, sx, sy);
    upk2(runB, sxx, syy);
    const float xm = sx * invn;
    const float ym = sy * invn;
    const float cross = fmaf(-xm, ym, rxy * invn);
    const float vx    = fmaf(-xm, xm, sxx * invn);
    const float vy    = fmaf(-ym, ym, syy * invn);
    return __fdividef(cross * cross, fmaf(vx, vy, 1e-5f));
}

// ================= pass 2 (R11): D sliding + NCC + reduce + finalize =========
__global__ __launch_bounds__(160, 6)
void lncc_pass2(float* __restrict__ out) {
    const int tid = threadIdx.x;         // 0..159
    const int ty  = tid / 80;            // h row
    const int txp = tid % 80;            // w pair
    const int h   = blockIdx.x * 2 + ty;
    const int dc  = blockIdx.y;
    const int b   = blockIdx.z;
    const int d0  = dc * DS;
    const int w0  = txp * 2;

    const size_t base = (size_t)b * VOLSZ + (size_t)h * WW + w0;

    auto sidx = [&](int jd) -> size_t {
        const int gd = iclamp(d0 - 4 + jd, DD - 1);
        return base + (size_t)gd * (HH * WW);
    };

    // depth-4 lead prefetch: one uint4 (2 records' A) + one uint (2 Sxy)
    uint4 pipeA[4];
    unsigned pipeC[4];
    #pragma unroll
    for (int i = 0; i < 4; ++i) {
        const size_t idx = sidx(i);
        pipeA[i] = __ldg(reinterpret_cast<const uint4*>(&g_scrA[idx]));
        pipeC[i] = __ldg(reinterpret_cast<const unsigned*>(&g_scrC[idx]));
    }

    ull runA0 = 0ull, runB0 = 0ull, runA1 = 0ull, runB1 = 0ull;
    float runxy0 = 0.f, runxy1 = 0.f;
    float acc = 0.f;

    auto consume = [&](int jd, bool trail, bool emit) {
        const uint4    A = pipeA[jd & 3];
        const unsigned C = pipeC[jd & 3];
        if (jd + 4 < STEPS) {
            const size_t idx = sidx(jd + 4);
            pipeA[jd & 3] = __ldg(reinterpret_cast<const uint4*>(&g_scrA[idx]));
            pipeC[jd & 3] = __ldg(reinterpret_cast<const unsigned*>(&g_scrC[idx]));
        }
        uint4 T = make_uint4(0u, 0u, 0u, 0u);
        unsigned Tc = 0u;
        if (trail) {                      // record from step jd-9: L1/L2 hit
            const size_t idx = sidx(jd - 9);
            T  = __ldg(reinterpret_cast<const uint4*>(&g_scrA[idx]));
            Tc = __ldg(reinterpret_cast<const unsigned*>(&g_scrC[idx]));
        }
        {
            const float2 a = h2f(A.x), oa = h2f(T.x);
            const float2 q = h2f(A.y), oq = h2f(T.y);
            runA0 = add2(runA0, sub2(pk2(a.x, a.y), pk2(oa.x, oa.y)));
            runB0 = add2(runB0, sub2(pk2(q.x, q.y), pk2(oq.x, oq.y)));
        }
        {
            const float2 a = h2f(A.z), oa = h2f(T.z);
            const float2 q = h2f(A.w), oq = h2f(T.w);
            runA1 = add2(runA1, sub2(pk2(a.x, a.y), pk2(oa.x, oa.y)));
            runB1 = add2(runB1, sub2(pk2(q.x, q.y), pk2(oq.x, oq.y)));
        }
        {
            const float2 c = h2f(C), oc = h2f(Tc);
            runxy0 += c.x - oc.x;
            runxy1 += c.y - oc.y;
        }
        if (emit) {
            acc += ncc_term(runA0, runB0, runxy0);
            acc += ncc_term(runA1, runB1, runxy1);
        }
    };

    #pragma unroll
    for (int jd = 0; jd < 8; ++jd) consume(jd, false, false);
    consume(8, false, true);
    #pragma unroll 8
    for (int jd = 9; jd < STEPS; ++jd) consume(jd, true, true);

    // block reduce (5 warps) -> double atomic -> fused finalize
    __shared__ float red[5];
    #pragma unroll
    for (int o = 16; o > 0; o >>= 1)
        acc += __shfl_down_sync(0xffffffffu, acc, o);
    const int warp = tid >> 5;
    const int lane = tid & 31;
    if (lane == 0) red[warp] = acc;
    __syncthreads();
    if (warp == 0 && lane == 0) {
        float v = red[0] + red[1] + red[2] + red[3] + red[4];
        atomicAdd(&g_acc, (double)v);
        __threadfence();
        const unsigned ticket = atomicAdd(&g_ctr, 1u);
        if (ticket == (unsigned)(P2_BLOCKS - 1)) {
            double total = atomicAdd(&g_acc, 0.0);   // ordered read
            out[0] = (float)(-total * (1.0 / (double)VOL2));
        }
    }
}

extern "C" void kernel_launch(void* const* d_in, const int* in_sizes, int n_in,
                              void* d_out, int out_size) {
    (void)in_sizes; (void)n_in; (void)out_size;
    const float* x = (const float*)d_in[0];
    const float* y = (const float*)d_in[1];
    float* out = (float*)d_out;

    dim3 g1(NH, DD / 2, BB);      // 4 x 80 x 2 = 640 blocks, 160 thr
    lncc_pass1<<<g1, 160>>>(x, y);

    dim3 g2(HH / 2, ND, BB);      // 80 x 8 x 2 = 1280 blocks, 160 thr
    lncc_pass2<<<g2, 160>>>(out);
}

// round 14
// speedup vs baseline: 1.2482x; 1.0034x over previous
#include <cuda_runtime.h>
#include <cuda_fp16.h>

// LNCC loss, two-pass separable:
//   pass1 (R8 shape): block = 2 d-planes x 80 w-pairs, H-strip 40 (NH=4).
//          cp.async 8-row ring (dist 6, wait_group 4), 2 rows/barrier.
//          Two adjacent 9-tap W sums per thread (shared taps, 5 LDS.128),
//          fp16-bit H sliding history -> 10 B/voxel fp16 scratch, stored
//          via createpolicy L2::evict_last cache_hint (keep L2-resident).
//   pass2 (R11 shape): thread owns 2 adjacent w cols, D-chunk 20 (ND=8),
//          depth-4 lead prefetch + L1-hit trail reload (jd-9), reg-capped.
//          NCC + fused reduction/finalize.

#define BB 2
#define DD 160
#define HH 160
#define WW 160
#define VOLSZ (DD*HH*WW)
#define VOL2  (BB*VOLSZ)

#define NH 4
#define HS (HH/NH)          // 40 output rows per block
#define ROWS (HS + 8)       // 48 row steps

#define ND 8
#define DS (DD/ND)          // 20
#define STEPS (DS + 8)      // 28

#define P2_BLOCKS ((HH/2) * ND * BB)   // 1280

__device__ __align__(16) uint2          g_scrA[VOL2];   // {half2(Sx,Sy), half2(Sxx,Syy)}
__device__ __align__(16) unsigned short g_scrC[VOL2];   // half(Sxy)
__device__ double g_acc;
__device__ unsigned int g_ctr;

// ---- packed f32x2 helpers (sm_100+) ----
typedef unsigned long long ull;
__device__ __forceinline__ ull pk2(float a, float b) {
    ull r; asm("mov.b64 %0, {%1, %2};" : "=l"(r) : "f"(a), "f"(b)); return r;
}
__device__ __forceinline__ void upk2(ull v, float& a, float& b) {
    asm("mov.b64 {%0, %1}, %2;" : "=f"(a), "=f"(b) : "l"(v));
}
__device__ __forceinline__ ull add2(ull a, ull b) {
    ull d; asm("add.rn.f32x2 %0, %1, %2;" : "=l"(d) : "l"(a), "l"(b)); return d;
}
__device__ __forceinline__ ull sub2(ull a, ull b) {
    ull d; asm("sub.rn.f32x2 %0, %1, %2;" : "=l"(d) : "l"(a), "l"(b)); return d;
}
__device__ __forceinline__ ull mul2(ull a, ull b) {
    ull d; asm("mul.rn.f32x2 %0, %1, %2;" : "=l"(d) : "l"(a), "l"(b)); return d;
}
__device__ __forceinline__ ull fma2(ull a, ull b, ull c) {
    ull d; asm("fma.rn.f32x2 %0, %1, %2, %3;" : "=l"(d) : "l"(a), "l"(b), "l"(c)); return d;
}

__device__ __forceinline__ int iclamp(int v, int hi) { return min(max(v, 0), hi); }

__device__ __forceinline__ float2 h2f(unsigned bits) {
    __half2 h = *reinterpret_cast<__half2*>(&bits);
    return __half22float2(h);
}
__device__ __forceinline__ unsigned f2hbits(float a, float b) {
    __half2 h = __floats2half2_rn(a, b);
    return *reinterpret_cast<unsigned*>(&h);
}

// ---- L2 evict_last via access policy (legal on sm_103 for any width) ----
__device__ __forceinline__ ull mkpolicy_evict_last() {
    ull p;
    asm("createpolicy.fractional.L2::evict_last.b64 %0, 1.0;" : "=l"(p));
    return p;
}
__device__ __forceinline__ void st_el_v4(void* p, uint4 v, ull pol) {
    asm volatile("st.global.L2::cache_hint.v4.u32 [%0], {%1, %2, %3, %4}, %5;"
                 :: "l"(p), "r"(v.x), "r"(v.y), "r"(v.z), "r"(v.w), "l"(pol)
                 : "memory");
}
__device__ __forceinline__ void st_el_u32(void* p, unsigned v, ull pol) {
    asm volatile("st.global.L2::cache_hint.u32 [%0], %1, %2;"
                 :: "l"(p), "r"(v), "l"(pol) : "memory");
}
__device__ __forceinline__ uint4 ld_el_v4(const void* p, ull pol) {
    uint4 v;
    asm volatile("ld.global.nc.L2::cache_hint.v4.u32 {%0, %1, %2, %3}, [%4], %5;"
                 : "=r"(v.x), "=r"(v.y), "=r"(v.z), "=r"(v.w)
                 : "l"(p), "l"(pol));
    return v;
}
__device__ __forceinline__ unsigned ld_el_u32(const void* p, ull pol) {
    unsigned v;
    asm volatile("ld.global.nc.L2::cache_hint.u32 %0, [%1], %2;"
                 : "=r"(v) : "l"(p), "l"(pol));
    return v;
}

__device__ __forceinline__ void cpa4(void* dst_smem, const void* src) {
    unsigned s = (unsigned)__cvta_generic_to_shared(dst_smem);
    asm volatile("cp.async.ca.shared.global [%0], [%1], 4;" :: "r"(s), "l"(src));
}
#define CPA_COMMIT() asm volatile("cp.async.commit_group;" ::: "memory")
#define CPA_WAIT4()  asm volatile("cp.async.wait_group 4;" ::: "memory")

// slide one packed field through fp16-bit history (exact add/sub round trip)
__device__ __forceinline__ void slide_p(ull s, unsigned& hist, ull& run) {
    float f0, f1; upk2(s, f0, f1);
    const unsigned nb = f2hbits(f0, f1);
    const float2 nf = h2f(nb);
    const float2 of = h2f(hist);
    run = add2(run, sub2(pk2(nf.x, nf.y), pk2(of.x, of.y)));
    hist = nb;
}
__device__ __forceinline__ unsigned pack_run(ull run) {
    float f0, f1; upk2(run, f0, f1);
    return f2hbits(f0, f1);
}

// ================= pass 1 =================
__global__ __launch_bounds__(160)
void lncc_pass1(const float* __restrict__ x, const float* __restrict__ y) {
    __shared__ __align__(16) float2 buf[2][8][WW + 8];

    const int tid = threadIdx.x;
    const int ty  = tid / 80;            // plane select
    const int txp = tid % 80;            // w pair
    const int w0  = txp * 2;

    const int strip = blockIdx.x;
    const int d     = blockIdx.y * 2 + ty;
    const int b     = blockIdx.z;
    const int hs0   = strip * HS;

    if (blockIdx.x == 0 && blockIdx.y == 0 && blockIdx.z == 0 && tid == 0) {
        g_acc = 0.0;
        g_ctr = 0u;
    }

    const ull pol = mkpolicy_evict_last();

    const float* xp = x + ((size_t)b * DD + d) * (HH * WW);
    const float* yp = y + ((size_t)b * DD + d) * (HH * WW);

    auto issue = [&](int r) {
        const int gh = iclamp(hs0 - 4 + r, HH - 1);
        const float* xr = xp + gh * WW;
        const float* yr = yp + gh * WW;
        float2* dst = buf[ty][r & 7];
        #pragma unroll
        for (int e0 = 0; e0 < 3; ++e0) {
            const int e = txp + e0 * 80;
            if (e < WW + 8) {
                const int gw = iclamp(e - 4, WW - 1);
                cpa4(&dst[e].x, xr + gw);
                cpa4(&dst[e].y, yr + gw);
            }
        }
        CPA_COMMIT();
    };

    issue(0); issue(1); issue(2); issue(3); issue(4); issue(5);

    // fp16-bit history: per column A=(Sx,Sy), B=(Sxx,Syy); shared XY pair
    unsigned hA0[9], hB0[9], hA1[9], hB1[9], hXY[9];
    #pragma unroll
    for (int k = 0; k < 9; ++k) { hA0[k]=0u; hB0[k]=0u; hA1[k]=0u; hB1[k]=0u; hXY[k]=0u; }
    ull rA0 = 0ull, rB0 = 0ull, rA1 = 0ull, rB1 = 0ull;
    float rxy0 = 0.f, rxy1 = 0.f;

    const size_t obase = ((size_t)b * DD + d) * (HH * WW) + w0;

    #pragma unroll
    for (int it = 0; it < ROWS / 2; ++it) {
        CPA_WAIT4();
        __syncthreads();

        if (2 * it + 6 < ROWS) issue(2 * it + 6); else CPA_COMMIT();
        if (2 * it + 7 < ROWS) issue(2 * it + 7); else CPA_COMMIT();

        #pragma unroll
        for (int sub = 0; sub < 2; ++sub) {
            const int r = 2 * it + sub;
            const float4* row4 = reinterpret_cast<const float4*>(buf[ty][r & 7]);

            // taps e = w0 .. w0+9  (float4 = two (x,y) pairs)
            const float4 q0 = row4[txp];
            const float4 q1 = row4[txp + 1];
            const float4 q2 = row4[txp + 2];
            const float4 q3 = row4[txp + 3];
            const float4 q4 = row4[txp + 4];

            const ull pp0 = pk2(q0.x, q0.y), pp1 = pk2(q0.z, q0.w);
            const ull pp2 = pk2(q1.x, q1.y), pp3 = pk2(q1.z, q1.w);
            const ull pp4 = pk2(q2.x, q2.y), pp5 = pk2(q2.z, q2.w);
            const ull pp6 = pk2(q3.x, q3.y), pp7 = pk2(q3.z, q3.w);
            const ull pp8 = pk2(q4.x, q4.y), pp9 = pk2(q4.z, q4.w);

            // column 0: taps 0..8
            ull s01 = add2(pp0, pp1);
            s01 = add2(s01, pp2); s01 = add2(s01, pp3); s01 = add2(s01, pp4);
            s01 = add2(s01, pp5); s01 = add2(s01, pp6); s01 = add2(s01, pp7);
            s01 = add2(s01, pp8);
            ull s23 = mul2(pp0, pp0);
            s23 = fma2(pp1, pp1, s23); s23 = fma2(pp2, pp2, s23);
            s23 = fma2(pp3, pp3, s23); s23 = fma2(pp4, pp4, s23);
            s23 = fma2(pp5, pp5, s23); s23 = fma2(pp6, pp6, s23);
            s23 = fma2(pp7, pp7, s23); s23 = fma2(pp8, pp8, s23);
            float sxy0 = q0.x * q0.y;
            sxy0 = fmaf(q0.z, q0.w, sxy0); sxy0 = fmaf(q1.x, q1.y, sxy0);
            sxy0 = fmaf(q1.z, q1.w, sxy0); sxy0 = fmaf(q2.x, q2.y, sxy0);
            sxy0 = fmaf(q2.z, q2.w, sxy0); sxy0 = fmaf(q3.x, q3.y, sxy0);
            sxy0 = fmaf(q3.z, q3.w, sxy0); sxy0 = fmaf(q4.x, q4.y, sxy0);

            // column 1: taps 1..9 = col0 - tap0 + tap9
            const ull s01b = add2(sub2(s01, pp0), pp9);
            const ull s23b = fma2(pp9, pp9, sub2(s23, mul2(pp0, pp0)));
            const float sxy1 = fmaf(q4.z, q4.w, fmaf(-q0.x, q0.y, sxy0));

            const int k = r % 9;   // static per unrolled iteration
            slide_p(s01,  hA0[k], rA0);
            slide_p(s23,  hB0[k], rB0);
            slide_p(s01b, hA1[k], rA1);
            slide_p(s23b, hB1[k], rB1);
            {
                const unsigned nb = f2hbits(sxy0, sxy1);
                const float2 nf = h2f(nb);
                const float2 of = h2f(hXY[k]);
                rxy0 += nf.x - of.x;
                rxy1 += nf.y - of.y;
                hXY[k] = nb;
            }

            if (r >= 8) {
                uint4 rec;
                rec.x = pack_run(rA0);
                rec.y = pack_run(rB0);
                rec.z = pack_run(rA1);
                rec.w = pack_run(rB1);
                const size_t o = obase + (size_t)(hs0 + r - 8) * WW;
                st_el_v4(&g_scrA[o], rec, pol);
                st_el_u32(&g_scrC[o], f2hbits(rxy0, rxy1), pol);
            }
        }
    }
}

// ================= pass 2 helpers =================
__device__ __forceinline__ float ncc_term(ull runA, ull runB, float rxy) {
    const float invn = 1.0f / 729.0f;
    float sx, sy, sxx, syy;
    upk2(runA, sx, sy);
    upk2(runB, sxx, syy);
    const float xm = sx * invn;
    const float ym = sy * invn;
    const float cross = fmaf(-xm, ym, rxy * invn);
    const float vx    = fmaf(-xm, xm, sxx * invn);
    const float vy    = fmaf(-ym, ym, syy * invn);
    return __fdividef(cross * cross, fmaf(vx, vy, 1e-5f));
}

// ================= pass 2: D sliding + NCC + reduce + finalize ===============
__global__ __launch_bounds__(160, 6)
void lncc_pass2(float* __restrict__ out) {
    const int tid = threadIdx.x;         // 0..159
    const int ty  = tid / 80;            // h row
    const int txp = tid % 80;            // w pair
    const int h   = blockIdx.x * 2 + ty;
    const int dc  = blockIdx.y;
    const int b   = blockIdx.z;
    const int d0  = dc * DS;
    const int w0  = txp * 2;

    const ull pol = mkpolicy_evict_last();

    const size_t base = (size_t)b * VOLSZ + (size_t)h * WW + w0;

    auto sidx = [&](int jd) -> size_t {
        const int gd = iclamp(d0 - 4 + jd, DD - 1);
        return base + (size_t)gd * (HH * WW);
    };

    // depth-4 lead prefetch: one uint4 (2 records' A) + one uint (2 Sxy)
    uint4 pipeA[4];
    unsigned pipeC[4];
    #pragma unroll
    for (int i = 0; i < 4; ++i) {
        const size_t idx = sidx(i);
        pipeA[i] = ld_el_v4(&g_scrA[idx], pol);
        pipeC[i] = ld_el_u32(&g_scrC[idx], pol);
    }

    ull runA0 = 0ull, runB0 = 0ull, runA1 = 0ull, runB1 = 0ull;
    float runxy0 = 0.f, runxy1 = 0.f;
    float acc = 0.f;

    auto consume = [&](int jd, bool trail, bool emit) {
        const uint4    A = pipeA[jd & 3];
        const unsigned C = pipeC[jd & 3];
        if (jd + 4 < STEPS) {
            const size_t idx = sidx(jd + 4);
            pipeA[jd & 3] = ld_el_v4(&g_scrA[idx], pol);
            pipeC[jd & 3] = ld_el_u32(&g_scrC[idx], pol);
        }
        uint4 T = make_uint4(0u, 0u, 0u, 0u);
        unsigned Tc = 0u;
        if (trail) {                      // record from step jd-9: L1/L2 hit
            const size_t idx = sidx(jd - 9);
            T  = __ldg(reinterpret_cast<const uint4*>(&g_scrA[idx]));
            Tc = __ldg(reinterpret_cast<const unsigned*>(&g_scrC[idx]));
        }
        {
            const float2 a = h2f(A.x), oa = h2f(T.x);
            const float2 q = h2f(A.y), oq = h2f(T.y);
            runA0 = add2(runA0, sub2(pk2(a.x, a.y), pk2(oa.x, oa.y)));
            runB0 = add2(runB0, sub2(pk2(q.x, q.y), pk2(oq.x, oq.y)));
        }
        {
            const float2 a = h2f(A.z), oa = h2f(T.z);
            const float2 q = h2f(A.w), oq = h2f(T.w);
            runA1 = add2(runA1, sub2(pk2(a.x, a.y), pk2(oa.x, oa.y)));
            runB1 = add2(runB1, sub2(pk2(q.x, q.y), pk2(oq.x, oq.y)));
        }
        {
            const float2 c = h2f(C), oc = h2f(Tc);
            runxy0 += c.x - oc.x;
            runxy1 += c.y - oc.y;
        }
        if (emit) {
            acc += ncc_term(runA0, runB0, runxy0);
            acc += ncc_term(runA1, runB1, runxy1);
        }
    };

    #pragma unroll
    for (int jd = 0; jd < 8; ++jd) consume(jd, false, false);
    consume(8, false, true);
    #pragma unroll 8
    for (int jd = 9; jd < STEPS; ++jd) consume(jd, true, true);

    // block reduce (5 warps) -> double atomic -> fused finalize
    __shared__ float red[5];
    #pragma unroll
    for (int o = 16; o > 0; o >>= 1)
        acc += __shfl_down_sync(0xffffffffu, acc, o);
    const int warp = tid >> 5;
    const int lane = tid & 31;
    if (lane == 0) red[warp] = acc;
    __syncthreads();
    if (warp == 0 && lane == 0) {
        float v = red[0] + red[1] + red[2] + red[3] + red[4];
        atomicAdd(&g_acc, (double)v);
        __threadfence();
        const unsigned ticket = atomicAdd(&g_ctr, 1u);
        if (ticket == (unsigned)(P2_BLOCKS - 1)) {
            double total = atomicAdd(&g_acc, 0.0);   // ordered read
            out[0] = (float)(-total * (1.0 / (double)VOL2));
        }
    }
}

extern "C" void kernel_launch(void* const* d_in, const int* in_sizes, int n_in,
                              void* d_out, int out_size) {
    (void)in_sizes; (void)n_in; (void)out_size;
    const float* x = (const float*)d_in[0];
    const float* y = (const float*)d_in[1];
    float* out = (float*)d_out;

    dim3 g1(NH, DD / 2, BB);      // 4 x 80 x 2 = 640 blocks, 160 thr
    lncc_pass1<<<g1, 160>>>(x, y);

    dim3 g2(HH / 2, ND, BB);      // 80 x 8 x 2 = 1280 blocks, 160 thr
    lncc_pass2<<<g2, 160>>>(out);
}